// round 2
// baseline (speedup 1.0000x reference)
#include <cuda_runtime.h>
#include <cstdint>

typedef unsigned long long ull;

#define BB 512
#define TT 1024
#define IDIM 15
#define HH 64
#define ODIM 11
#define CHUNK2 16
#define NCHUNK2 (TT/CHUNK2)

// scratch (static __device__ — no allocations in kernel_launch)
__device__ __align__(16) float g_xproj[(size_t)BB*TT*HH];   // x @ W_ih^T + b_ih + b_hh

// ---- f32x2 helpers (FFMA2 path: 2 fp32 FMAs per instruction) ----
__device__ __forceinline__ ull ffma2(ull a, ull b, ull c){
    ull d; asm("fma.rn.f32x2 %0, %1, %2, %3;" : "=l"(d) : "l"(a), "l"(b), "l"(c)); return d;
}
__device__ __forceinline__ ull fadd2(ull a, ull b){
    ull d; asm("add.rn.f32x2 %0, %1, %2;" : "=l"(d) : "l"(a), "l"(b)); return d;
}
__device__ __forceinline__ ull pack2(float x, float y){
    ull r; asm("mov.b64 %0, {%1, %2};" : "=l"(r) : "f"(x), "f"(y)); return r;
}
__device__ __forceinline__ float2 unpack2(ull v){
    float2 r; asm("mov.b64 {%0, %1}, %2;" : "=f"(r.x), "=f"(r.y) : "l"(v)); return r;
}

// ---- kernel 0: xproj[b,t,:] = x[b,t,:] @ W_ih^T + (b_ih + b_hh). Memory-bound GEMM. ----
__global__ void __launch_bounds__(256) xproj_kernel(
    const float* __restrict__ x, const float* __restrict__ W_ih,
    const float* __restrict__ b_ih, const float* __restrict__ b_hh)
{
    __shared__ __align__(16) float xs[64][16];   // 64 rows, padded to 16
    const int tid = threadIdx.x;
    const int l = tid & 31, w = tid >> 5;
    const int j0 = 2*l, j1 = j0 + 1;

    // W_ih rows j0,j1 in registers, i-paired (i=15 padded with 0)
    ull wi0[8], wi1[8];
    #pragma unroll
    for (int q=0;q<8;q++){
        float a0 = W_ih[j0*IDIM + 2*q];
        float a1 = (2*q+1 < IDIM) ? W_ih[j0*IDIM + 2*q + 1] : 0.f;
        wi0[q] = pack2(a0,a1);
        float c0 = W_ih[j1*IDIM + 2*q];
        float c1 = (2*q+1 < IDIM) ? W_ih[j1*IDIM + 2*q + 1] : 0.f;
        wi1[q] = pack2(c0,c1);
    }
    const float bias0 = b_ih[j0] + b_hh[j0];
    const float bias1 = b_ih[j1] + b_hh[j1];

    const size_t row0 = (size_t)blockIdx.x * 64;
    const float* xsrc = x + row0 * IDIM;
    #pragma unroll
    for (int i = tid; i < 64*IDIM; i += 256) xs[i/IDIM][i%IDIM] = xsrc[i];
    if (tid < 64) xs[tid][15] = 0.f;
    __syncthreads();

    ull* dst = ((ull*)g_xproj) + row0 * 32;
    #pragma unroll
    for (int r=0;r<8;r++){
        const int row = w*8 + r;
        const ull* xv = (const ull*)xs[row];    // 64B-aligned rows
        ull a0 = pack2(bias0, 0.f), a1 = pack2(bias1, 0.f);
        #pragma unroll
        for (int q=0;q<8;q++){
            a0 = ffma2(xv[q], wi0[q], a0);
            a1 = ffma2(xv[q], wi1[q], a1);
        }
        float2 s0 = unpack2(a0), s1 = unpack2(a1);
        dst[(size_t)row*32 + l] = pack2(s0.x+s0.y, s1.x+s1.y);   // STG.64 coalesced
    }
}

// ---- kernel 1: fused recurrence + decoder. warp == one batch row ----
__global__ void __launch_bounds__(128,1) rnn_dec_kernel(
    const float* __restrict__ W_hh,
    const float* __restrict__ W_dec, const float* __restrict__ b_dec,
    float* __restrict__ out, float* __restrict__ h_out)
{
    __shared__ __align__(16) float xps[2][4][CHUNK2*64];   // double-buffered xproj chunks (32KB)
    __shared__ __align__(16) ull  h_sh[4][2][32];          // per-warp double-buffered h

    const int wid = threadIdx.x >> 5;
    const int l   = threadIdx.x & 31;
    const int b   = blockIdx.x * 4 + wid;
    const int j0  = 2*l, j1 = j0 + 1;

    // W_hh rows j0,j1 in registers, k-paired as f32x2
    ull w0[32], w1[32];
    {
        const ull* wp = (const ull*)W_hh;
        #pragma unroll
        for (int q=0;q<32;q++){ w0[q] = wp[j0*32+q]; w1[q] = wp[j1*32+q]; }
    }

    // decoder weights: lane l<22 handles output o=l>>1, K-half = l&1 (16 ull each)
    const int o = l >> 1, half = l & 1;
    ull wd[16];
    float bdec = 0.f;
    if (l < 22){
        const ull* wdp = (const ull*)W_dec;
        #pragma unroll
        for (int q=0;q<16;q++) wd[q] = wdp[o*32 + half*16 + q];
        bdec = b_dec[o];
    } else {
        #pragma unroll
        for (int q=0;q<16;q++) wd[q] = 0ULL;
    }

    h_sh[wid][1][l] = 0ULL;   // h_{-1} = 0 (t=0 reads slot 1)

    const uint32_t xs_base = (uint32_t)__cvta_generic_to_shared(&xps[0][wid][0]);
    const float* xsrc = g_xproj + (size_t)b * (TT*HH);

    auto prefetch = [&](int c){
        if (c < NCHUNK2){
            const float* src = xsrc + (size_t)c * (CHUNK2*HH);
            uint32_t dst = xs_base + (uint32_t)(c & 1) * (uint32_t)sizeof(xps[0]);
            #pragma unroll
            for (int q=0;q<8;q++){
                asm volatile("cp.async.ca.shared.global [%0], [%1], 16;\n"
                    :: "r"(dst + (uint32_t)((q*32+l)*16)), "l"(src + (q*32+l)*4) : "memory");
            }
        }
        asm volatile("cp.async.commit_group;\n" ::: "memory");
    };

    prefetch(0);

    float* outp = out + (size_t)b * (TT*ODIM);

    for (int c=0; c<NCHUNK2; c++){
        prefetch(c+1);                                         // overlap next chunk
        asm volatile("cp.async.wait_group 1;\n" ::: "memory"); // chunk c landed
        __syncwarp();
        const float* xpb = &xps[c & 1][wid][0];

        #pragma unroll 2
        for (int tt=0; tt<CHUNK2; tt++){
            const int rs = (tt & 1) ^ 1;   // slot holding h_{t-1}
            const int ws =  tt & 1;        // slot for h_t
            const int t  = c*CHUNK2 + tt;

            // xproj slice for this lane's two outputs (conflict-free LDS.64)
            ull xp = ((const ull*)xpb)[tt*32 + l];

            // recurrence: 64 f32x2 FMAs over full h_{t-1} (broadcast LDS.128)
            const ulonglong2* hp = (const ulonglong2*)&h_sh[wid][rs][0];
            ull aa0=0ULL, aa1=0ULL, ab0=0ULL, ab1=0ULL;
            #pragma unroll
            for (int q=0;q<16;q++){
                ulonglong2 hv = hp[q];
                aa0 = ffma2(hv.x, w0[2*q],   aa0);
                aa1 = ffma2(hv.x, w1[2*q],   aa1);
                ab0 = ffma2(hv.y, w0[2*q+1], ab0);
                ab1 = ffma2(hv.y, w1[2*q+1], ab1);
            }

            // decoder for h_{t-1} (emitted at index t-1); lane reads its K-half
            const ulonglong2* hd = (const ulonglong2*)&h_sh[wid][rs][half*16];
            ull d0=0ULL, d1=0ULL;
            #pragma unroll
            for (int q=0;q<8;q++){
                ulonglong2 hv = hd[q];
                d0 = ffma2(hv.x, wd[2*q],   d0);
                d1 = ffma2(hv.y, wd[2*q+1], d1);
            }
            float2 ds = unpack2(fadd2(d0,d1));
            float dp = ds.x + ds.y;
            float dq = __shfl_down_sync(0xffffffffu, dp, 1);

            // finalize recurrence
            float2 s0 = unpack2(fadd2(aa0, ab0));
            float2 s1 = unpack2(fadd2(aa1, ab1));
            float2 xv = unpack2(xp);
            float h0v = fmaxf(s0.x + s0.y + xv.x, 0.f);
            float h1v = fmaxf(s1.x + s1.y + xv.y, 0.f);
            h_sh[wid][ws][l] = pack2(h0v, h1v);

            // store decoder output for step t-1 (skip the bogus t=0 value)
            if (t > 0 && l < 22 && half == 0){
                outp[(size_t)(t-1)*ODIM + o] = fmaxf(dp + dq + bdec, 0.f);
            }
            __syncwarp();
        }
    }

    // final decoder for t = T-1 (h_{1023} lives in slot 1) + final hidden state
    {
        const ulonglong2* hd = (const ulonglong2*)&h_sh[wid][1][half*16];
        ull d0=0ULL, d1=0ULL;
        #pragma unroll
        for (int q=0;q<8;q++){
            ulonglong2 hv = hd[q];
            d0 = ffma2(hv.x, wd[2*q],   d0);
            d1 = ffma2(hv.y, wd[2*q+1], d1);
        }
        float2 ds = unpack2(fadd2(d0,d1));
        float dp = ds.x + ds.y;
        float dq = __shfl_down_sync(0xffffffffu, dp, 1);
        if (l < 22 && half == 0){
            outp[(size_t)(TT-1)*ODIM + o] = fmaxf(dp + dq + bdec, 0.f);
        }
        // final hidden state -> tail of d_out ( [1,B,H] )
        ((ull*)h_out)[b*32 + l] = h_sh[wid][1][l];
    }
}

extern "C" void kernel_launch(void* const* d_in, const int* in_sizes, int n_in,
                              void* d_out, int out_size)
{
    const float* x     = (const float*)d_in[0];
    const float* W_ih  = (const float*)d_in[1];
    const float* b_ih  = (const float*)d_in[2];
    const float* W_hh  = (const float*)d_in[3];
    const float* b_hh  = (const float*)d_in[4];
    const float* W_dec = (const float*)d_in[5];
    const float* b_dec = (const float*)d_in[6];
    float* out = (float*)d_out;

    (void)in_sizes; (void)n_in; (void)out_size;

    // kernel 0: input projection (+fused biases), memory-bound
    xproj_kernel<<<(BB*TT)/64, 256>>>(x, W_ih, b_ih, b_hh);
    // kernel 1: fused recurrence + decoder; writes out [B,T,O] and final h tail
    rnn_dec_kernel<<<BB/4, 128>>>(W_hh, W_dec, b_dec, out, out + (size_t)BB*TT*ODIM);
}